// round 2
// baseline (speedup 1.0000x reference)
#include <cuda_runtime.h>
#include <cstdint>

#define BATCH 4096
#define TMAX  2048
#define HID   32

typedef unsigned long long ull;

__device__ int g_perm[BATCH];

// ---------------- fast math helpers ----------------
__device__ __forceinline__ float fast_ex2(float x) {
    float y; asm("ex2.approx.f32 %0, %1;" : "=f"(y) : "f"(x)); return y;
}
__device__ __forceinline__ float fast_rcp(float x) {
    float y; asm("rcp.approx.f32 %0, %1;" : "=f"(y) : "f"(x)); return y;
}
__device__ __forceinline__ float sigmoidf_fast(float x) {
    // 1 / (1 + 2^(-x*log2(e)))
    return fast_rcp(1.0f + fast_ex2(-1.4426950408889634f * x));
}
__device__ __forceinline__ float tanhf_fast(float x) {
    // 2/(1+2^(-2x*log2e)) - 1
    return fmaf(2.0f, fast_rcp(1.0f + fast_ex2(-2.8853900817779268f * x)), -1.0f);
}
__device__ __forceinline__ float expf_fast(float x) {
    return fast_ex2(1.4426950408889634f * x);
}
__device__ __forceinline__ void fma2(ull& d, ull a, ull b) {
    asm("fma.rn.f32x2 %0, %1, %2, %0;" : "+l"(d) : "l"(a), "l"(b));
}
__device__ __forceinline__ float hsum2(ull v) {
    float lo = __uint_as_float((unsigned)(v & 0xffffffffu));
    float hi = __uint_as_float((unsigned)(v >> 32));
    return lo + hi;
}

// ---------------- counting sort: longest sequence first ----------------
__global__ void sort_by_len_kernel(const int* __restrict__ lengths) {
    __shared__ int cnt[TMAX];
    __shared__ int tmp[TMAX];
    int tid = threadIdx.x;           // 1024 threads
    for (int i = tid; i < TMAX; i += 1024) cnt[i] = 0;
    __syncthreads();
    for (int i = tid; i < BATCH; i += 1024) {
        int key = TMAX - lengths[i];  // len in [1,2048] -> key in [0,2047], longest first
        atomicAdd(&cnt[key], 1);
    }
    __syncthreads();
    // Hillis-Steele inclusive scan over 2048 bins (double buffer)
    int* src = cnt;
    int* dst = tmp;
    for (int off = 1; off < TMAX; off <<= 1) {
        for (int i = tid; i < TMAX; i += 1024) {
            int v = src[i];
            if (i >= off) v += src[i - off];
            dst[i] = v;
        }
        __syncthreads();
        int* t = src; src = dst; dst = t;
    }
    // exclusive offsets into dst
    for (int i = tid; i < TMAX; i += 1024) dst[i] = (i == 0) ? 0 : src[i - 1];
    __syncthreads();
    for (int i = tid; i < BATCH; i += 1024) {
        int key = TMAX - lengths[i];
        int pos = atomicAdd(&dst[key], 1);
        g_perm[pos] = i;
    }
}

// ---------------- main kernel: one warp (one CTA of 32) per batch element ----------------
__global__ void __launch_bounds__(32) bilstm_kernel(
    const float* __restrict__ x,
    const int*   __restrict__ lengths,
    const float* __restrict__ w_ih,
    const float* __restrict__ w_hh,
    const float* __restrict__ b_ih,
    const float* __restrict__ b_hh,
    const float* __restrict__ fc_w,
    const float* __restrict__ fc_b,
    const float* __restrict__ fc2_w,
    const float* __restrict__ fc2_b,
    float* __restrict__ out)
{
    __shared__ __align__(16) float sh[2][HID];
    const int lane = threadIdx.x;
    const int b    = g_perm[blockIdx.x];
    const int L    = lengths[b];

    // register-resident recurrent weights: lane j holds rows j, j+32, j+64, j+96 (i,f,g,o)
    ull wi[16], wf[16], wg[16], wo[16];
    const ull* W = (const ull*)w_hh;   // row r: 16 packed pairs at r*16
    #pragma unroll
    for (int p = 0; p < 16; p++) {
        wi[p] = W[(lane      ) * 16 + p];
        wf[p] = W[(lane + 32 ) * 16 + p];
        wg[p] = W[(lane + 64 ) * 16 + p];
        wo[p] = W[(lane + 96 ) * 16 + p];
    }
    const float wih_i = w_ih[lane],      wih_f = w_ih[lane + 32];
    const float wih_g = w_ih[lane + 64], wih_o = w_ih[lane + 96];
    const float bi = b_ih[lane]      + b_hh[lane];
    const float bf = b_ih[lane + 32] + b_hh[lane + 32];
    const float bg = b_ih[lane + 64] + b_hh[lane + 64];
    const float bo = b_ih[lane + 96] + b_hh[lane + 96];

    sh[0][lane] = 0.0f;
    sh[1][lane] = 0.0f;
    __syncwarp();

    float c = 0.0f;
    int cur = 0;
    const float* xb = x + (size_t)b * TMAX;

    // --- chunked coalesced prefetch of x: one LDG.32 per lane per 32 steps ---
    int t = L - 1;
    int cbase = t & ~31;                 // base of chunk containing t
    float xcur  = __ldg(xb + cbase + lane);
    float xnext = (cbase >= 32) ? __ldg(xb + cbase - 32 + lane) : 0.0f;

    for (; t >= 0; --t) {
        const float xt = __shfl_sync(0xffffffffu, xcur, t & 31);

        const ull* hb = (const ull*)sh[cur];
        ull ai = 0, af = 0, ag = 0, ao = 0;
        #pragma unroll
        for (int p = 0; p < 16; p++) {
            ull hv = hb[p];                 // broadcast LDS.64
            fma2(ai, wi[p], hv);
            fma2(af, wf[p], hv);
            fma2(ag, wg[p], hv);
            fma2(ao, wo[p], hv);
        }
        const float gi = hsum2(ai) + fmaf(xt, wih_i, bi);
        const float gf = hsum2(af) + fmaf(xt, wih_f, bf);
        const float gg = hsum2(ag) + fmaf(xt, wih_g, bg);
        const float go = hsum2(ao) + fmaf(xt, wih_o, bo);

        const float I = sigmoidf_fast(gi);
        const float F = sigmoidf_fast(gf);
        const float G = tanhf_fast(gg);
        const float O = sigmoidf_fast(go);

        c = fmaf(F, c, I * G);
        const float hj = O * tanhf_fast(c);

        cur ^= 1;
        sh[cur][lane] = hj;
        __syncwarp();

        if ((t & 31) == 0) {                    // crossing into the next (earlier) chunk
            xcur  = xnext;
            cbase -= 32;
            xnext = (cbase >= 32) ? __ldg(xb + cbase - 32 + lane) : 0.0f;
        }
    }

    // ---------------- MLP head (h replicated through smem) ----------------
    const float* hfin = sh[cur];
    float acc0 = __ldg(fc_b + lane);
    float acc1 = __ldg(fc_b + lane + 32);
    #pragma unroll
    for (int k = 0; k < HID; k++) {
        const float hk = hfin[k];
        acc0 = fmaf(__ldg(fc_w + lane * HID + k),        hk, acc0);
        acc1 = fmaf(__ldg(fc_w + (lane + 32) * HID + k), hk, acc1);
    }
    const float e0 = (acc0 > 0.0f) ? acc0 : (expf_fast(acc0) - 1.0f);
    const float e1 = (acc1 > 0.0f) ? acc1 : (expf_fast(acc1) - 1.0f);
    float p = e0 * __ldg(fc2_w + lane) + e1 * __ldg(fc2_w + lane + 32);
    #pragma unroll
    for (int off = 16; off > 0; off >>= 1)
        p += __shfl_xor_sync(0xffffffffu, p, off);
    if (lane == 0)
        out[b] = sigmoidf_fast(p + __ldg(fc2_b));
}

extern "C" void kernel_launch(void* const* d_in, const int* in_sizes, int n_in,
                              void* d_out, int out_size) {
    const float* x     = (const float*)d_in[0];
    const int*   lens  = (const int*)  d_in[1];
    const float* w_ih  = (const float*)d_in[2];
    const float* w_hh  = (const float*)d_in[3];
    const float* b_ih  = (const float*)d_in[4];
    const float* b_hh  = (const float*)d_in[5];
    const float* fc_w  = (const float*)d_in[6];
    const float* fc_b  = (const float*)d_in[7];
    const float* fc2_w = (const float*)d_in[8];
    const float* fc2_b = (const float*)d_in[9];
    float* out = (float*)d_out;

    sort_by_len_kernel<<<1, 1024>>>(lens);
    bilstm_kernel<<<BATCH, 32>>>(x, lens, w_ih, w_hh, b_ih, b_hh,
                                 fc_w, fc_b, fc2_w, fc2_b, out);
}